// round 4
// baseline (speedup 1.0000x reference)
#include <cuda_runtime.h>
#include <cstdint>
#include <climits>

#define NUM_MASKS 64
#define MH 1024
#define MW 1024
#define NTHREADS 256
#define CHUNKS_PER_MASK 128                     // chunk = 8 contiguous rows = 32KB
#define NCHUNKS (NUM_MASKS * CHUNKS_PER_MASK)   // 8192
#define ROWS_PER_CHUNK 8
#define GRID 1216                               // 152 SMs * 8 blocks, one wave
#define AREA_THRESH 1024   // (1024/32)*(1024/32); keep = count > AREA_THRESH

// Per-chunk partials. Every slot written every launch -> no init needed.
__device__ int g_pminx[NCHUNKS];
__device__ int g_pminy[NCHUNKS];
__device__ int g_pmaxx[NCHUNKS];
__device__ int g_pmaxy[NCHUNKS];
__device__ int g_pcnt [NCHUNKS];
// Dynamic scheduling + completion counters (reset by finalizer each launch).
__device__ unsigned int g_chunk  = GRID;  // first GRID chunks taken statically
__device__ unsigned int g_arrive = 0;

__global__ __launch_bounds__(NTHREADS, 8) void fsam_fused_kernel(
    const float* __restrict__ masks, float* __restrict__ out) {

    const int tid  = threadIdx.x;
    const int wid  = tid >> 5;
    const int lane = tid & 31;
    const int colbase = tid << 2;

    __shared__ int s_minx[8], s_miny[8], s_maxx[8], s_maxy[8], s_cnt[8];
    __shared__ unsigned s_next;
    __shared__ unsigned s_last;

    const uint4* __restrict__ base = reinterpret_cast<const uint4*>(masks);

    int c = blockIdx.x;  // first chunk statically assigned
    while (c < NCHUNKS) {
        // Prefetch next chunk id (hidden behind this chunk's loads)
        if (tid == 0) s_next = atomicAdd(&g_chunk, 1u);

        const int mask = c >> 7;          // / CHUNKS_PER_MASK
        const int sub  = c & 127;
        // chunk covers rows [sub*8, sub*8+8), contiguous 32KB
        const uint4* __restrict__ p =
            base + (size_t)mask * ((MH * MW) / 4) + sub * (ROWS_PER_CHUNK * 256) + tid;

        uint4 cm = make_uint4(0u, 0u, 0u, 0u);
        unsigned rowmask = 0u;
        float fc0 = 0.f, fc1 = 0.f, fc2 = 0.f, fc3 = 0.f;

        #pragma unroll
        for (int j = 0; j < ROWS_PER_CHUNK; j++) {
            uint4 v = p[j * 256];
            cm.x |= v.x; cm.y |= v.y; cm.z |= v.z; cm.w |= v.w;
            unsigned any = (v.x | v.y) | (v.z | v.w);
            rowmask |= (unsigned)(any != 0u) << j;
            fc0 += __uint_as_float(v.x);
            fc1 += __uint_as_float(v.y);
            fc2 += __uint_as_float(v.z);
            fc3 += __uint_as_float(v.w);
        }

        int cnt = (int)((fc0 + fc1) + (fc2 + fc3));
        unsigned mbits =  (unsigned)(cm.x != 0u)
                       | ((unsigned)(cm.y != 0u) << 1)
                       | ((unsigned)(cm.z != 0u) << 2)
                       | ((unsigned)(cm.w != 0u) << 3);

        int minx, maxx, miny, maxy;
        if (mbits) { minx = colbase + (__ffs(mbits) - 1); maxx = colbase + (31 - __clz(mbits)); }
        else       { minx = INT_MAX;                      maxx = -1; }
        const int row0 = sub * ROWS_PER_CHUNK;
        if (rowmask) {
            miny = row0 + (__ffs(rowmask) - 1);
            maxy = row0 + (31 - __clz(rowmask));
        } else { miny = INT_MAX; maxy = -1; }

        #pragma unroll
        for (int off = 16; off > 0; off >>= 1) {
            minx = min(minx, __shfl_down_sync(0xFFFFFFFFu, minx, off));
            miny = min(miny, __shfl_down_sync(0xFFFFFFFFu, miny, off));
            maxx = max(maxx, __shfl_down_sync(0xFFFFFFFFu, maxx, off));
            maxy = max(maxy, __shfl_down_sync(0xFFFFFFFFu, maxy, off));
            cnt +=           __shfl_down_sync(0xFFFFFFFFu, cnt,  off);
        }
        if (lane == 0) {
            s_minx[wid] = minx; s_miny[wid] = miny;
            s_maxx[wid] = maxx; s_maxy[wid] = maxy;
            s_cnt [wid] = cnt;
        }
        __syncthreads();
        if (tid == 0) {
            int bminx = s_minx[0], bminy = s_miny[0];
            int bmaxx = s_maxx[0], bmaxy = s_maxy[0];
            int bcnt  = s_cnt[0];
            #pragma unroll
            for (int j = 1; j < NTHREADS / 32; j++) {
                bminx = min(bminx, s_minx[j]);
                bminy = min(bminy, s_miny[j]);
                bmaxx = max(bmaxx, s_maxx[j]);
                bmaxy = max(bmaxy, s_maxy[j]);
                bcnt += s_cnt[j];
            }
            g_pminx[c] = bminx;
            g_pminy[c] = bminy;
            g_pmaxx[c] = bmaxx;
            g_pmaxy[c] = bmaxy;
            g_pcnt [c] = bcnt;
        }
        __syncthreads();   // s_next ready, smem partials consumed
        c = (int)s_next;
    }

    // Block done: arrive. Last block finalizes.
    if (tid == 0) {
        __threadfence();
        s_last = atomicAdd(&g_arrive, 1u);
    }
    __syncthreads();

    if (s_last == GRID - 1) {
        __threadfence();  // acquire all partials
        // 256 threads: 4 threads per mask, each covers 32 of 128 chunk-partials.
        const int m = tid >> 2;
        const int p = tid & 3;
        int fminx = INT_MAX, fminy = INT_MAX, fmaxx = -1, fmaxy = -1, fcnt = 0;
        const int b0 = m * CHUNKS_PER_MASK + p * 32;
        #pragma unroll 8
        for (int k = 0; k < 32; k++) {
            int idx = b0 + k;
            fminx = min(fminx, g_pminx[idx]);
            fminy = min(fminy, g_pminy[idx]);
            fmaxx = max(fmaxx, g_pmaxx[idx]);
            fmaxy = max(fmaxy, g_pmaxy[idx]);
            fcnt += g_pcnt[idx];
        }
        #pragma unroll
        for (int off = 2; off > 0; off >>= 1) {
            fminx = min(fminx, __shfl_down_sync(0xFFFFFFFFu, fminx, off));
            fminy = min(fminy, __shfl_down_sync(0xFFFFFFFFu, fminy, off));
            fmaxx = max(fmaxx, __shfl_down_sync(0xFFFFFFFFu, fmaxx, off));
            fmaxy = max(fmaxy, __shfl_down_sync(0xFFFFFFFFu, fmaxy, off));
            fcnt +=            __shfl_down_sync(0xFFFFFFFFu, fcnt,  off);
        }
        if (p == 0) {
            float4 b = (fcnt > AREA_THRESH)
                ? make_float4((float)fminx, (float)fminy, (float)fmaxx, (float)fmaxy)
                : make_float4(0.f, 0.f, 0.f, 0.f);
            reinterpret_cast<float4*>(out)[m] = b;
        }
        if (tid == 0) {           // reset for next graph replay
            g_chunk  = GRID;
            g_arrive = 0;
        }
    }
}

extern "C" void kernel_launch(void* const* d_in, const int* in_sizes, int n_in,
                              void* d_out, int out_size) {
    const float* masks = (const float*)d_in[0];
    float* out = (float*)d_out;
    fsam_fused_kernel<<<GRID, NTHREADS>>>(masks, out);
}

// round 5
// speedup vs baseline: 1.3871x; 1.3871x over previous
#include <cuda_runtime.h>
#include <cstdint>
#include <climits>

#define NUM_MASKS 64
#define MH 1024
#define MW 1024
#define NTHREADS 256
#define BLOCKS_PER_MASK 19
#define GRID (NUM_MASKS * BLOCKS_PER_MASK)   // 1216 = 152 SMs * 8 blocks: one wave
#define CHUNKS_PER_MASK 128                  // chunk = 8 contiguous rows
#define ROWS_PER_CHUNK 8
#define UINT4_PER_MASK ((MH * MW) / 4)       // 262144
#define AREA_THRESH 1024   // (1024/32)*(1024/32); keep = count > AREA_THRESH

// Per-block partials. Every slot written every launch -> no init needed.
__device__ int g_pminx[GRID];
__device__ int g_pminy[GRID];
__device__ int g_pmaxx[GRID];
__device__ int g_pmaxy[GRID];
__device__ int g_pcnt [GRID];
// Completion counter (reset by finalizer each launch for graph replay).
__device__ unsigned int g_arrive = 0;

__global__ __launch_bounds__(NTHREADS, 8) void fsam_fused_kernel(
    const float* __restrict__ masks, float* __restrict__ out) {

    const int tid  = threadIdx.x;
    const int wid  = tid >> 5;
    const int lane = tid & 31;
    const int colbase = tid << 2;

    const int mask = blockIdx.x & 63;   // b % 64
    const int bsub = blockIdx.x >> 6;   // b / 64, 0..18

    const uint4* __restrict__ mbase =
        reinterpret_cast<const uint4*>(masks) + (size_t)mask * UINT4_PER_MASK + tid;

    // Accumulators that live across ALL chunks (no barriers until the end):
    uint4 cm = make_uint4(0u, 0u, 0u, 0u);   // column OR (thread col = tid*4, constant)
    int miny = INT_MAX, maxy = -1;
    float fc0 = 0.f, fc1 = 0.f, fc2 = 0.f, fc3 = 0.f;

    // Chunks sub = bsub, bsub+19, ... < 128 : 8 contiguous rows each, no barriers.
    for (int sub = bsub; sub < CHUNKS_PER_MASK; sub += BLOCKS_PER_MASK) {
        const uint4* __restrict__ p = mbase + sub * (ROWS_PER_CHUNK * 256);
        unsigned rowmask = 0u;
        #pragma unroll
        for (int j = 0; j < ROWS_PER_CHUNK; j++) {
            uint4 v = p[j * 256];
            cm.x |= v.x; cm.y |= v.y; cm.z |= v.z; cm.w |= v.w;
            unsigned any = (v.x | v.y) | (v.z | v.w);
            rowmask |= (unsigned)(any != 0u) << j;
            fc0 += __uint_as_float(v.x);
            fc1 += __uint_as_float(v.y);
            fc2 += __uint_as_float(v.z);
            fc3 += __uint_as_float(v.w);
        }
        if (rowmask) {
            const int row0 = sub * ROWS_PER_CHUNK;
            miny = min(miny, row0 + (__ffs(rowmask) - 1));
            maxy = max(maxy, row0 + (31 - __clz(rowmask)));
        }
    }

    int cnt = (int)((fc0 + fc1) + (fc2 + fc3));
    unsigned mbits =  (unsigned)(cm.x != 0u)
                   | ((unsigned)(cm.y != 0u) << 1)
                   | ((unsigned)(cm.z != 0u) << 2)
                   | ((unsigned)(cm.w != 0u) << 3);
    int minx, maxx;
    if (mbits) { minx = colbase + (__ffs(mbits) - 1); maxx = colbase + (31 - __clz(mbits)); }
    else       { minx = INT_MAX;                      maxx = -1; }

    // ---- single block reduction ----
    #pragma unroll
    for (int off = 16; off > 0; off >>= 1) {
        minx = min(minx, __shfl_down_sync(0xFFFFFFFFu, minx, off));
        miny = min(miny, __shfl_down_sync(0xFFFFFFFFu, miny, off));
        maxx = max(maxx, __shfl_down_sync(0xFFFFFFFFu, maxx, off));
        maxy = max(maxy, __shfl_down_sync(0xFFFFFFFFu, maxy, off));
        cnt +=           __shfl_down_sync(0xFFFFFFFFu, cnt,  off);
    }

    __shared__ int s_minx[8], s_miny[8], s_maxx[8], s_maxy[8], s_cnt[8];
    __shared__ unsigned s_last;
    if (lane == 0) {
        s_minx[wid] = minx; s_miny[wid] = miny;
        s_maxx[wid] = maxx; s_maxy[wid] = maxy;
        s_cnt [wid] = cnt;
    }
    __syncthreads();

    if (tid == 0) {
        int bminx = s_minx[0], bminy = s_miny[0];
        int bmaxx = s_maxx[0], bmaxy = s_maxy[0];
        int bcnt  = s_cnt[0];
        #pragma unroll
        for (int j = 1; j < NTHREADS / 32; j++) {
            bminx = min(bminx, s_minx[j]);
            bminy = min(bminy, s_miny[j]);
            bmaxx = max(bmaxx, s_maxx[j]);
            bmaxy = max(bmaxy, s_maxy[j]);
            bcnt += s_cnt[j];
        }
        g_pminx[blockIdx.x] = bminx;
        g_pminy[blockIdx.x] = bminy;
        g_pmaxx[blockIdx.x] = bmaxx;
        g_pmaxy[blockIdx.x] = bmaxy;
        g_pcnt [blockIdx.x] = bcnt;
        __threadfence();
        s_last = atomicAdd(&g_arrive, 1u);
    }
    __syncthreads();

    // ---- tail block: finalize ----
    if (s_last == GRID - 1) {
        __threadfence();  // acquire all partials
        // 256 threads: 4 threads per mask, each covers <=5 of the 19 partials.
        const int m = tid >> 2;
        const int p = tid & 3;
        int fminx = INT_MAX, fminy = INT_MAX, fmaxx = -1, fmaxy = -1, fcnt = 0;
        for (int bs = p; bs < BLOCKS_PER_MASK; bs += 4) {
            int idx = m + (bs << 6);            // block id = mask + 64*bsub
            fminx = min(fminx, g_pminx[idx]);
            fminy = min(fminy, g_pminy[idx]);
            fmaxx = max(fmaxx, g_pmaxx[idx]);
            fmaxy = max(fmaxy, g_pmaxy[idx]);
            fcnt += g_pcnt[idx];
        }
        #pragma unroll
        for (int off = 2; off > 0; off >>= 1) {
            fminx = min(fminx, __shfl_down_sync(0xFFFFFFFFu, fminx, off));
            fminy = min(fminy, __shfl_down_sync(0xFFFFFFFFu, fminy, off));
            fmaxx = max(fmaxx, __shfl_down_sync(0xFFFFFFFFu, fmaxx, off));
            fmaxy = max(fmaxy, __shfl_down_sync(0xFFFFFFFFu, fmaxy, off));
            fcnt +=            __shfl_down_sync(0xFFFFFFFFu, fcnt,  off);
        }
        if (p == 0) {
            float4 b = (fcnt > AREA_THRESH)
                ? make_float4((float)fminx, (float)fminy, (float)fmaxx, (float)fmaxy)
                : make_float4(0.f, 0.f, 0.f, 0.f);
            reinterpret_cast<float4*>(out)[m] = b;
        }
        if (tid == 0) g_arrive = 0;  // reset for next graph replay
    }
}

extern "C" void kernel_launch(void* const* d_in, const int* in_sizes, int n_in,
                              void* d_out, int out_size) {
    const float* masks = (const float*)d_in[0];
    float* out = (float*)d_out;
    fsam_fused_kernel<<<GRID, NTHREADS>>>(masks, out);
}

// round 6
// speedup vs baseline: 1.4089x; 1.0157x over previous
#include <cuda_runtime.h>
#include <cstdint>
#include <climits>

#define NUM_MASKS 64
#define MH 1024
#define MW 1024
#define NTHREADS 256
#define BLOCKS_PER_MASK 16
#define GRID (NUM_MASKS * BLOCKS_PER_MASK)   // 1024 <= 152*8 capacity: fully co-resident
#define ROWS_PER_BLOCK 64                    // contiguous 256KB slab per block
#define ROWS_PER_CHUNK 8
#define CHUNKS_PER_BLOCK (ROWS_PER_BLOCK / ROWS_PER_CHUNK)   // 8
#define UINT4_PER_MASK ((MH * MW) / 4)       // 262144
#define AREA_THRESH 1024   // (1024/32)*(1024/32); keep = count > AREA_THRESH

// Per-block partials. Every slot written every launch -> no init needed.
__device__ int g_pminx[GRID];
__device__ int g_pminy[GRID];
__device__ int g_pmaxx[GRID];
__device__ int g_pmaxy[GRID];
__device__ int g_pcnt [GRID];
// Completion counter (reset by finalizer each launch for graph replay).
__device__ unsigned int g_arrive = 0;

__global__ __launch_bounds__(NTHREADS, 8) void fsam_fused_kernel(
    const float* __restrict__ masks, float* __restrict__ out) {

    const int tid  = threadIdx.x;
    const int wid  = tid >> 5;
    const int lane = tid & 31;
    const int colbase = tid << 2;

    const int mask = blockIdx.x >> 4;   // / BLOCKS_PER_MASK
    const int bsub = blockIdx.x & 15;
    const int row0 = bsub * ROWS_PER_BLOCK;

    // Contiguous slab: rows [row0, row0+64) of this mask = 256KB sequential.
    const uint4* __restrict__ p =
        reinterpret_cast<const uint4*>(masks)
        + (size_t)mask * UINT4_PER_MASK + row0 * 256 + tid;

    // Thread column constant (tid*4): column-OR accumulates across everything.
    uint4 cm = make_uint4(0u, 0u, 0u, 0u);
    int miny = INT_MAX, maxy = -1;
    float fc0 = 0.f, fc1 = 0.f, fc2 = 0.f, fc3 = 0.f;

    #pragma unroll
    for (int k = 0; k < CHUNKS_PER_BLOCK; k++) {
        unsigned rowmask = 0u;
        #pragma unroll
        for (int j = 0; j < ROWS_PER_CHUNK; j++) {
            uint4 v = p[(k * ROWS_PER_CHUNK + j) * 256];
            cm.x |= v.x; cm.y |= v.y; cm.z |= v.z; cm.w |= v.w;
            unsigned any = (v.x | v.y) | (v.z | v.w);
            rowmask |= (unsigned)(any != 0u) << j;
            fc0 += __uint_as_float(v.x);
            fc1 += __uint_as_float(v.y);
            fc2 += __uint_as_float(v.z);
            fc3 += __uint_as_float(v.w);
        }
        if (rowmask) {
            const int r = row0 + k * ROWS_PER_CHUNK;
            miny = min(miny, r + (__ffs(rowmask) - 1));
            maxy = max(maxy, r + (31 - __clz(rowmask)));
        }
    }

    int cnt = (int)((fc0 + fc1) + (fc2 + fc3));
    unsigned mbits =  (unsigned)(cm.x != 0u)
                   | ((unsigned)(cm.y != 0u) << 1)
                   | ((unsigned)(cm.z != 0u) << 2)
                   | ((unsigned)(cm.w != 0u) << 3);
    int minx, maxx;
    if (mbits) { minx = colbase + (__ffs(mbits) - 1); maxx = colbase + (31 - __clz(mbits)); }
    else       { minx = INT_MAX;                      maxx = -1; }

    // ---- single block reduction ----
    #pragma unroll
    for (int off = 16; off > 0; off >>= 1) {
        minx = min(minx, __shfl_down_sync(0xFFFFFFFFu, minx, off));
        miny = min(miny, __shfl_down_sync(0xFFFFFFFFu, miny, off));
        maxx = max(maxx, __shfl_down_sync(0xFFFFFFFFu, maxx, off));
        maxy = max(maxy, __shfl_down_sync(0xFFFFFFFFu, maxy, off));
        cnt +=           __shfl_down_sync(0xFFFFFFFFu, cnt,  off);
    }

    __shared__ int s_minx[8], s_miny[8], s_maxx[8], s_maxy[8], s_cnt[8];
    __shared__ unsigned s_last;
    if (lane == 0) {
        s_minx[wid] = minx; s_miny[wid] = miny;
        s_maxx[wid] = maxx; s_maxy[wid] = maxy;
        s_cnt [wid] = cnt;
    }
    __syncthreads();

    if (tid == 0) {
        int bminx = s_minx[0], bminy = s_miny[0];
        int bmaxx = s_maxx[0], bmaxy = s_maxy[0];
        int bcnt  = s_cnt[0];
        #pragma unroll
        for (int j = 1; j < NTHREADS / 32; j++) {
            bminx = min(bminx, s_minx[j]);
            bminy = min(bminy, s_miny[j]);
            bmaxx = max(bmaxx, s_maxx[j]);
            bmaxy = max(bmaxy, s_maxy[j]);
            bcnt += s_cnt[j];
        }
        g_pminx[blockIdx.x] = bminx;
        g_pminy[blockIdx.x] = bminy;
        g_pmaxx[blockIdx.x] = bmaxx;
        g_pmaxy[blockIdx.x] = bmaxy;
        g_pcnt [blockIdx.x] = bcnt;
        __threadfence();
        s_last = atomicAdd(&g_arrive, 1u);
    }
    __syncthreads();

    // ---- tail block: finalize ----
    if (s_last == GRID - 1) {
        __threadfence();  // acquire all partials
        // 256 threads: 4 threads per mask, each covers 4 of 16 partials.
        const int m = tid >> 2;
        const int p4 = tid & 3;
        int fminx = INT_MAX, fminy = INT_MAX, fmaxx = -1, fmaxy = -1, fcnt = 0;
        #pragma unroll
        for (int k = 0; k < 4; k++) {
            int idx = m * BLOCKS_PER_MASK + p4 + 4 * k;
            fminx = min(fminx, g_pminx[idx]);
            fminy = min(fminy, g_pminy[idx]);
            fmaxx = max(fmaxx, g_pmaxx[idx]);
            fmaxy = max(fmaxy, g_pmaxy[idx]);
            fcnt += g_pcnt[idx];
        }
        #pragma unroll
        for (int off = 2; off > 0; off >>= 1) {
            fminx = min(fminx, __shfl_down_sync(0xFFFFFFFFu, fminx, off));
            fminy = min(fminy, __shfl_down_sync(0xFFFFFFFFu, fminy, off));
            fmaxx = max(fmaxx, __shfl_down_sync(0xFFFFFFFFu, fmaxx, off));
            fmaxy = max(fmaxy, __shfl_down_sync(0xFFFFFFFFu, fmaxy, off));
            fcnt +=            __shfl_down_sync(0xFFFFFFFFu, fcnt,  off);
        }
        if (p4 == 0) {
            float4 b = (fcnt > AREA_THRESH)
                ? make_float4((float)fminx, (float)fminy, (float)fmaxx, (float)fmaxy)
                : make_float4(0.f, 0.f, 0.f, 0.f);
            reinterpret_cast<float4*>(out)[m] = b;
        }
        if (tid == 0) g_arrive = 0;  // reset for next graph replay
    }
}

extern "C" void kernel_launch(void* const* d_in, const int* in_sizes, int n_in,
                              void* d_out, int out_size) {
    const float* masks = (const float*)d_in[0];
    float* out = (float*)d_out;
    fsam_fused_kernel<<<GRID, NTHREADS>>>(masks, out);
}

// round 7
// speedup vs baseline: 1.4098x; 1.0007x over previous
#include <cuda_runtime.h>
#include <cstdint>
#include <climits>

#define NUM_MASKS 64
#define MH 1024
#define MW 1024
#define NTHREADS 256
#define BLOCKS_PER_MASK 16
#define GRID (NUM_MASKS * BLOCKS_PER_MASK)   // 1024 <= 152*8 capacity: fully co-resident
#define ROWS_PER_BLOCK 64                    // contiguous 256KB slab per block
#define ROWS_PER_CHUNK 8
#define CHUNKS_PER_BLOCK (ROWS_PER_BLOCK / ROWS_PER_CHUNK)   // 8
#define UINT4_PER_MASK ((MH * MW) / 4)       // 262144
#define AREA_THRESH 1024   // (1024/32)*(1024/32); keep = count > AREA_THRESH

// Per-block partials. Every slot written every launch -> no init needed.
__device__ int g_pminx[GRID];
__device__ int g_pminy[GRID];
__device__ int g_pmaxx[GRID];
__device__ int g_pmaxy[GRID];
__device__ int g_pcnt [GRID];
// Per-mask arrival counters; each mask's finalizer resets its own counter,
// so every graph replay starts from zero. Deterministic: 16 arrivals/mask.
__device__ unsigned int g_marrive[NUM_MASKS];  // zero-initialized once

__global__ __launch_bounds__(NTHREADS, 8) void fsam_fused_kernel(
    const float* __restrict__ masks, float* __restrict__ out) {

    const int tid  = threadIdx.x;
    const int wid  = tid >> 5;
    const int lane = tid & 31;
    const int colbase = tid << 2;

    const int mask = blockIdx.x >> 4;   // / BLOCKS_PER_MASK
    const int bsub = blockIdx.x & 15;
    const int row0 = bsub * ROWS_PER_BLOCK;

    // Contiguous slab: rows [row0, row0+64) of this mask = 256KB sequential.
    const uint4* __restrict__ p =
        reinterpret_cast<const uint4*>(masks)
        + (size_t)mask * UINT4_PER_MASK + row0 * 256 + tid;

    // Thread column constant (tid*4): column-OR accumulates across everything.
    uint4 cm = make_uint4(0u, 0u, 0u, 0u);
    int miny = INT_MAX, maxy = -1;
    float fc0 = 0.f, fc1 = 0.f, fc2 = 0.f, fc3 = 0.f;

    #pragma unroll
    for (int k = 0; k < CHUNKS_PER_BLOCK; k++) {
        unsigned rowmask = 0u;
        #pragma unroll
        for (int j = 0; j < ROWS_PER_CHUNK; j++) {
            uint4 v = p[(k * ROWS_PER_CHUNK + j) * 256];
            cm.x |= v.x; cm.y |= v.y; cm.z |= v.z; cm.w |= v.w;
            unsigned any = (v.x | v.y) | (v.z | v.w);
            rowmask |= (unsigned)(any != 0u) << j;
            fc0 += __uint_as_float(v.x);
            fc1 += __uint_as_float(v.y);
            fc2 += __uint_as_float(v.z);
            fc3 += __uint_as_float(v.w);
        }
        if (rowmask) {
            const int r = row0 + k * ROWS_PER_CHUNK;
            miny = min(miny, r + (__ffs(rowmask) - 1));
            maxy = max(maxy, r + (31 - __clz(rowmask)));
        }
    }

    int cnt = (int)((fc0 + fc1) + (fc2 + fc3));
    unsigned mbits =  (unsigned)(cm.x != 0u)
                   | ((unsigned)(cm.y != 0u) << 1)
                   | ((unsigned)(cm.z != 0u) << 2)
                   | ((unsigned)(cm.w != 0u) << 3);
    int minx, maxx;
    if (mbits) { minx = colbase + (__ffs(mbits) - 1); maxx = colbase + (31 - __clz(mbits)); }
    else       { minx = INT_MAX;                      maxx = -1; }

    // ---- single block reduction ----
    #pragma unroll
    for (int off = 16; off > 0; off >>= 1) {
        minx = min(minx, __shfl_down_sync(0xFFFFFFFFu, minx, off));
        miny = min(miny, __shfl_down_sync(0xFFFFFFFFu, miny, off));
        maxx = max(maxx, __shfl_down_sync(0xFFFFFFFFu, maxx, off));
        maxy = max(maxy, __shfl_down_sync(0xFFFFFFFFu, maxy, off));
        cnt +=           __shfl_down_sync(0xFFFFFFFFu, cnt,  off);
    }

    __shared__ int s_minx[8], s_miny[8], s_maxx[8], s_maxy[8], s_cnt[8];
    if (lane == 0) {
        s_minx[wid] = minx; s_miny[wid] = miny;
        s_maxx[wid] = maxx; s_maxy[wid] = maxy;
        s_cnt [wid] = cnt;
    }
    __syncthreads();

    // Warp 0 only from here: publish partial, arrive on per-mask counter,
    // last-arriving block finalizes its mask (no global tail, no extra sync).
    if (wid == 0) {
        unsigned pos = 0;
        if (lane == 0) {
            int bminx = s_minx[0], bminy = s_miny[0];
            int bmaxx = s_maxx[0], bmaxy = s_maxy[0];
            int bcnt  = s_cnt[0];
            #pragma unroll
            for (int j = 1; j < NTHREADS / 32; j++) {
                bminx = min(bminx, s_minx[j]);
                bminy = min(bminy, s_miny[j]);
                bmaxx = max(bmaxx, s_maxx[j]);
                bmaxy = max(bmaxy, s_maxy[j]);
                bcnt += s_cnt[j];
            }
            g_pminx[blockIdx.x] = bminx;
            g_pminy[blockIdx.x] = bminy;
            g_pmaxx[blockIdx.x] = bmaxx;
            g_pmaxy[blockIdx.x] = bmaxy;
            g_pcnt [blockIdx.x] = bcnt;
            __threadfence();   // partials visible before arrival
            pos = atomicAdd(&g_marrive[mask], 1u);
        }
        pos = __shfl_sync(0xFFFFFFFFu, pos, 0);

        if (pos == BLOCKS_PER_MASK - 1) {
            __threadfence();   // acquire: see all 16 partials of this mask
            int fminx = INT_MAX, fminy = INT_MAX, fmaxx = -1, fmaxy = -1, fcnt = 0;
            if (lane < BLOCKS_PER_MASK) {
                const int idx = mask * BLOCKS_PER_MASK + lane;
                fminx = g_pminx[idx];
                fminy = g_pminy[idx];
                fmaxx = g_pmaxx[idx];
                fmaxy = g_pmaxy[idx];
                fcnt  = g_pcnt [idx];
            }
            #pragma unroll
            for (int off = 8; off > 0; off >>= 1) {
                fminx = min(fminx, __shfl_down_sync(0xFFFFFFFFu, fminx, off));
                fminy = min(fminy, __shfl_down_sync(0xFFFFFFFFu, fminy, off));
                fmaxx = max(fmaxx, __shfl_down_sync(0xFFFFFFFFu, fmaxx, off));
                fmaxy = max(fmaxy, __shfl_down_sync(0xFFFFFFFFu, fmaxy, off));
                fcnt +=            __shfl_down_sync(0xFFFFFFFFu, fcnt,  off);
            }
            if (lane == 0) {
                float4 b = (fcnt > AREA_THRESH)
                    ? make_float4((float)fminx, (float)fminy, (float)fmaxx, (float)fmaxy)
                    : make_float4(0.f, 0.f, 0.f, 0.f);
                reinterpret_cast<float4*>(out)[mask] = b;
                g_marrive[mask] = 0;   // reset for next graph replay
            }
        }
    }
}

extern "C" void kernel_launch(void* const* d_in, const int* in_sizes, int n_in,
                              void* d_out, int out_size) {
    const float* masks = (const float*)d_in[0];
    float* out = (float*)d_out;
    fsam_fused_kernel<<<GRID, NTHREADS>>>(masks, out);
}

// round 8
// speedup vs baseline: 1.4494x; 1.0281x over previous
#include <cuda_runtime.h>
#include <cstdint>
#include <climits>

#define NUM_MASKS 64
#define MH 1024
#define MW 1024
#define NTHREADS 256
#define BLOCKS_PER_MASK 19
#define GRID (NUM_MASKS * BLOCKS_PER_MASK)   // 1216 = 152 SMs * 8 blocks exactly
#define UINT4_PER_MASK ((MH * MW) / 4)       // 262144
#define AREA_THRESH 1024   // (1024/32)*(1024/32); keep = count > AREA_THRESH

// Per-block partials. Every slot written every launch -> no init needed.
__device__ int g_pminx[GRID];
__device__ int g_pminy[GRID];
__device__ int g_pmaxx[GRID];
__device__ int g_pmaxy[GRID];
__device__ int g_pcnt [GRID];
// Per-mask arrival counters; each mask's finalizer resets its own counter.
__device__ unsigned int g_marrive[NUM_MASKS];  // zero-initialized once

__global__ __launch_bounds__(NTHREADS, 8) void fsam_fused_kernel(
    const float* __restrict__ masks, float* __restrict__ out) {

    const int tid  = threadIdx.x;
    const int wid  = tid >> 5;
    const int lane = tid & 31;
    const int colbase = tid << 2;

    const int mask = blockIdx.x / BLOCKS_PER_MASK;
    const int bsub = blockIdx.x - mask * BLOCKS_PER_MASK;

    // Contiguous uneven slab: rows [bsub*1024/19, (bsub+1)*1024/19) -> 53 or 54 rows.
    const int row_start = (bsub * MH) / BLOCKS_PER_MASK;
    const int row_end   = ((bsub + 1) * MH) / BLOCKS_PER_MASK;

    const uint4* __restrict__ mbase =
        reinterpret_cast<const uint4*>(masks) + (size_t)mask * UINT4_PER_MASK + tid;

    // Thread column constant (tid*4): column-OR accumulates across everything.
    uint4 cm = make_uint4(0u, 0u, 0u, 0u);
    int miny = INT_MAX, maxy = -1;
    float fc0 = 0.f, fc1 = 0.f, fc2 = 0.f, fc3 = 0.f;

    int r = row_start;
    // Fast path: unrolled 8-row chunks, barrier-free, back-to-back LDG.128.
    for (; r + 8 <= row_end; r += 8) {
        const uint4* __restrict__ p = mbase + r * 256;
        unsigned rowmask = 0u;
        #pragma unroll
        for (int j = 0; j < 8; j++) {
            uint4 v = p[j * 256];
            cm.x |= v.x; cm.y |= v.y; cm.z |= v.z; cm.w |= v.w;
            unsigned any = (v.x | v.y) | (v.z | v.w);
            rowmask |= (unsigned)(any != 0u) << j;
            fc0 += __uint_as_float(v.x);
            fc1 += __uint_as_float(v.y);
            fc2 += __uint_as_float(v.z);
            fc3 += __uint_as_float(v.w);
        }
        if (rowmask) {
            miny = min(miny, r + (__ffs(rowmask) - 1));
            maxy = max(maxy, r + (31 - __clz(rowmask)));
        }
    }
    // Tail: up to 7 single rows.
    for (; r < row_end; r++) {
        uint4 v = mbase[r * 256];
        cm.x |= v.x; cm.y |= v.y; cm.z |= v.z; cm.w |= v.w;
        if ((v.x | v.y) | (v.z | v.w)) {
            miny = min(miny, r);
            maxy = max(maxy, r);
        }
        fc0 += __uint_as_float(v.x);
        fc1 += __uint_as_float(v.y);
        fc2 += __uint_as_float(v.z);
        fc3 += __uint_as_float(v.w);
    }

    int cnt = (int)((fc0 + fc1) + (fc2 + fc3));
    unsigned mbits =  (unsigned)(cm.x != 0u)
                   | ((unsigned)(cm.y != 0u) << 1)
                   | ((unsigned)(cm.z != 0u) << 2)
                   | ((unsigned)(cm.w != 0u) << 3);
    int minx, maxx;
    if (mbits) { minx = colbase + (__ffs(mbits) - 1); maxx = colbase + (31 - __clz(mbits)); }
    else       { minx = INT_MAX;                      maxx = -1; }

    // ---- single block reduction ----
    #pragma unroll
    for (int off = 16; off > 0; off >>= 1) {
        minx = min(minx, __shfl_down_sync(0xFFFFFFFFu, minx, off));
        miny = min(miny, __shfl_down_sync(0xFFFFFFFFu, miny, off));
        maxx = max(maxx, __shfl_down_sync(0xFFFFFFFFu, maxx, off));
        maxy = max(maxy, __shfl_down_sync(0xFFFFFFFFu, maxy, off));
        cnt +=           __shfl_down_sync(0xFFFFFFFFu, cnt,  off);
    }

    __shared__ int s_minx[8], s_miny[8], s_maxx[8], s_maxy[8], s_cnt[8];
    if (lane == 0) {
        s_minx[wid] = minx; s_miny[wid] = miny;
        s_maxx[wid] = maxx; s_maxy[wid] = maxy;
        s_cnt [wid] = cnt;
    }
    __syncthreads();

    // Warp 0: publish partial, arrive on per-mask counter; the 19th block
    // of each mask reduces that mask's partials and writes its bbox.
    if (wid == 0) {
        unsigned pos = 0;
        if (lane == 0) {
            int bminx = s_minx[0], bminy = s_miny[0];
            int bmaxx = s_maxx[0], bmaxy = s_maxy[0];
            int bcnt  = s_cnt[0];
            #pragma unroll
            for (int j = 1; j < NTHREADS / 32; j++) {
                bminx = min(bminx, s_minx[j]);
                bminy = min(bminy, s_miny[j]);
                bmaxx = max(bmaxx, s_maxx[j]);
                bmaxy = max(bmaxy, s_maxy[j]);
                bcnt += s_cnt[j];
            }
            g_pminx[blockIdx.x] = bminx;
            g_pminy[blockIdx.x] = bminy;
            g_pmaxx[blockIdx.x] = bmaxx;
            g_pmaxy[blockIdx.x] = bmaxy;
            g_pcnt [blockIdx.x] = bcnt;
            __threadfence();   // partials visible before arrival
            pos = atomicAdd(&g_marrive[mask], 1u);
        }
        pos = __shfl_sync(0xFFFFFFFFu, pos, 0);

        if (pos == BLOCKS_PER_MASK - 1) {
            __threadfence();   // acquire: see all partials of this mask
            int fminx = INT_MAX, fminy = INT_MAX, fmaxx = -1, fmaxy = -1, fcnt = 0;
            if (lane < BLOCKS_PER_MASK) {
                const int idx = mask * BLOCKS_PER_MASK + lane;
                fminx = g_pminx[idx];
                fminy = g_pminy[idx];
                fmaxx = g_pmaxx[idx];
                fmaxy = g_pmaxy[idx];
                fcnt  = g_pcnt [idx];
            }
            #pragma unroll
            for (int off = 16; off > 0; off >>= 1) {
                fminx = min(fminx, __shfl_down_sync(0xFFFFFFFFu, fminx, off));
                fminy = min(fminy, __shfl_down_sync(0xFFFFFFFFu, fminy, off));
                fmaxx = max(fmaxx, __shfl_down_sync(0xFFFFFFFFu, fmaxx, off));
                fmaxy = max(fmaxy, __shfl_down_sync(0xFFFFFFFFu, fmaxy, off));
                fcnt +=            __shfl_down_sync(0xFFFFFFFFu, fcnt,  off);
            }
            if (lane == 0) {
                float4 b = (fcnt > AREA_THRESH)
                    ? make_float4((float)fminx, (float)fminy, (float)fmaxx, (float)fmaxy)
                    : make_float4(0.f, 0.f, 0.f, 0.f);
                reinterpret_cast<float4*>(out)[mask] = b;
                g_marrive[mask] = 0;   // reset for next graph replay
            }
        }
    }
}

extern "C" void kernel_launch(void* const* d_in, const int* in_sizes, int n_in,
                              void* d_out, int out_size) {
    const float* masks = (const float*)d_in[0];
    float* out = (float*)d_out;
    fsam_fused_kernel<<<GRID, NTHREADS>>>(masks, out);
}